// round 12
// baseline (speedup 1.0000x reference)
#include <cuda_runtime.h>
#include <cuda_bf16.h>
#include <cstdint>

#define N 8192
#define D 128
#define NB 128                   // 64-row blocks per dimension
#define NCTAS 8256               // NB*(NB+1)/2 triangular block pairs
#define LDS 136                  // feature tile smem row stride (bf16)
#define FN_SCALE 4.539815982f    // sqrt(log2(e)/0.07)

// dynamic smem layout (bytes)
#define A_OFF  0u                // A tile 64x136 bf16 (17408); reused as eT
#define B_OFF  17408u            // B tile 64x136 bf16 (17408)
#define M_OFF  34816u            // 2 half mask buffers, 18432 each
#define MH_SZ  18432u            // per-half: P(32x288) + Q(32x288)
#define MH_Q   9216u             // Q offset within a half buffer
#define MROW   288u              // mask smem row stride (72 words, 8 mod 32)
#define ETROW  144u              // eT row stride bytes
#define SMEM_BYTES 71680

#define NTHREADS 256

__device__ __nv_bfloat16 g_fn[N * D];
__device__ float g_pos[N];
__device__ float g_neg[N];

__device__ __forceinline__ float ex2f(float x) {
    float y;
    asm("ex2.approx.ftz.f32 %0, %1;" : "=f"(y) : "f"(x));
    return y;
}

// mask (0/1) -> float via single IMAD: bits = m * 0x3F800000
__device__ __forceinline__ float m2f(int m) {
    return __int_as_float(m * 0x3F800000);
}

__device__ __forceinline__ void prefetch_l2(const void* p) {
    asm volatile("prefetch.global.L2 [%0];" :: "l"(p));
}

__device__ __forceinline__ void barh(int h) {
    asm volatile("bar.sync %0, 128;" :: "r"(h + 1) : "memory");
}

__device__ __forceinline__ void mma16816(float d[4], const uint32_t a[4],
                                         uint32_t b0, uint32_t b1) {
    asm volatile(
        "mma.sync.aligned.m16n8k16.row.col.f32.bf16.bf16.f32 "
        "{%0,%1,%2,%3}, {%4,%5,%6,%7}, {%8,%9}, {%0,%1,%2,%3};"
        : "+f"(d[0]), "+f"(d[1]), "+f"(d[2]), "+f"(d[3])
        : "r"(a[0]), "r"(a[1]), "r"(a[2]), "r"(a[3]), "r"(b0), "r"(b1));
}

__device__ __forceinline__ void cp16(uint32_t dst, const void* src) {
    asm volatile("cp.async.cg.shared.global [%0], [%1], 16;" :: "r"(dst), "l"(src));
}

// decode upper-triangular 64-block pair index k -> (I, J), 0 <= I <= J < 128
__device__ __forceinline__ void decode_pair(int k, int& I, int& J) {
    I = (int)((257.0f - sqrtf(66049.0f - 8.0f * (float)k)) * 0.5f);
    while ((I * (257 - I)) / 2 > k) I--;
    while (((I + 1) * (256 - I)) / 2 <= k) I++;
    J = I + (k - (I * (257 - I)) / 2);
}

// ---------------------------------------------------------------------------
// Kernel 1: L2-normalize rows (exp scale folded) + zero accumulators.
// ---------------------------------------------------------------------------
__global__ void normalize_kernel(const float* __restrict__ f) {
    int z = blockIdx.x * 256 + threadIdx.x;
    if (z < N) g_pos[z] = 0.f;
    else if (z < 2 * N) g_neg[z - N] = 0.f;

    int warp = threadIdx.x >> 5, lane = threadIdx.x & 31;
    int row0 = blockIdx.x * 16 + warp * 2;
    const float4 v0 = ((const float4*)(f + (size_t)row0 * D))[lane];
    const float4 v1 = ((const float4*)(f + (size_t)(row0 + 1) * D))[lane];
    float s0 = v0.x * v0.x + v0.y * v0.y + v0.z * v0.z + v0.w * v0.w;
    float s1 = v1.x * v1.x + v1.y * v1.y + v1.z * v1.z + v1.w * v1.w;
#pragma unroll
    for (int o = 16; o > 0; o >>= 1) {
        s0 += __shfl_xor_sync(0xffffffffu, s0, o);
        s1 += __shfl_xor_sync(0xffffffffu, s1, o);
    }
    float r0 = FN_SCALE / fmaxf(sqrtf(s0), 1e-8f);
    float r1 = FN_SCALE / fmaxf(sqrtf(s1), 1e-8f);
    union { __nv_bfloat16 h[4]; uint2 u; } p0, p1;
    p0.h[0] = __float2bfloat16_rn(v0.x * r0);
    p0.h[1] = __float2bfloat16_rn(v0.y * r0);
    p0.h[2] = __float2bfloat16_rn(v0.z * r0);
    p0.h[3] = __float2bfloat16_rn(v0.w * r0);
    p1.h[0] = __float2bfloat16_rn(v1.x * r1);
    p1.h[1] = __float2bfloat16_rn(v1.y * r1);
    p1.h[2] = __float2bfloat16_rn(v1.z * r1);
    p1.h[3] = __float2bfloat16_rn(v1.w * r1);
    ((uint2*)(g_fn + (size_t)row0 * D))[lane] = p0.u;
    ((uint2*)(g_fn + (size_t)(row0 + 1) * D))[lane] = p1.u;
}

// ---------------------------------------------------------------------------
// Kernel 2: 64x64 block-pair Gram tiles, 256 thr/CTA, 3 CTAs/SM.
// Pass 1: rows in I-block x cols in J-block. Pass 2 (I!=J): transpose via eT.
// MMA: warp w -> rows (w>>1)*16..+16, cols (w&1)*32..+32. acc[4][4].
// Half h = tid>>7 owns pass-1 rows h*32..+32 and pass-2 rows h*32..+32.
// ---------------------------------------------------------------------------
__global__ __launch_bounds__(NTHREADS, 3) void simloss_sym(const int* __restrict__ pm,
                                                           const int* __restrict__ nm) {
    extern __shared__ __align__(16) char smem[];
    const uint32_t base = (uint32_t)__cvta_generic_to_shared(smem);
    const int tid = threadIdx.x;
    const int w = tid >> 5, l = tid & 31;
    const int wr = w >> 1, wc = w & 1;
    const int h = tid >> 7;               // half id 0..1
    const int tq = tid & 127;
    const uint32_t MB = base + M_OFF + (uint32_t)h * MH_SZ;

    int I, J;
    decode_pair(blockIdx.x, I, J);
    const int m0 = I * 64, j0 = J * 64;
    const bool isDiag = (I == J);

    // ---- t0 L2 prefetch: pass-1 block (m0,j0) + pass-2 block (j0,m0) ----
    {
        int L = tid;                      // 256 lines = 64 rows x 2 segs x 2 masks
        const int* msk = (L & 1) ? nm : pm;
        int seg = (L >> 1) & 1, r = L >> 2;
        prefetch_l2(msk + (size_t)(m0 + r) * N + j0 + seg * 32);
        if (!isDiag)
            prefetch_l2(msk + (size_t)(j0 + r) * N + m0 + seg * 32);
    }

    // ---- feature tiles: A (64 I-rows), B (64 J-rows) ----
#pragma unroll
    for (int k2 = 0; k2 < 4; k2++) {
        int i = tid + k2 * 256;           // 0..1023 chunks
        int r = i >> 4, c = i & 15;
        cp16(base + A_OFF + (uint32_t)((r * LDS + c * 8) * 2),
             g_fn + (size_t)(m0 + r) * D + c * 8);
        cp16(base + B_OFF + (uint32_t)((r * LDS + c * 8) * 2),
             g_fn + (size_t)(j0 + r) * D + c * 8);
    }
    asm volatile("cp.async.commit_group;");

    // ---- pass-1 masks: half h copies rows m0+h*32..+32, cols j0..+64, P+Q ----
#pragma unroll
    for (int k2 = 0; k2 < 8; k2++) {
        int i = tq + k2 * 128;            // 0..1023 chunks
        const int* mp = (i & 512) ? nm : pm;
        uint32_t moff = (i & 512) ? MH_Q : 0u;
        int r = (i >> 4) & 31, ch = i & 15;
        cp16(MB + moff + (uint32_t)r * MROW + (uint32_t)ch * 16,
             mp + (size_t)(m0 + h * 32 + r) * N + j0 + ch * 4);
    }
    asm volatile("cp.async.commit_group;");

    asm volatile("cp.async.wait_group 1;");   // features ready; masks in flight
    __syncthreads();

    // ---- MMA: 16 rows x 32 cols per warp, A frags in two k-halves ----
    float acc[4][4];
#pragma unroll
    for (int i = 0; i < 4; i++) {
        acc[i][0] = 0.f; acc[i][1] = 0.f; acc[i][2] = 0.f; acc[i][3] = 0.f;
    }
    const int ar = wr * 16 + (l & 15);
    const int ac = (l >> 4) * 8;
    const int brow = (l >> 4) * 8 + (l & 7);
    const int bcol = ((l >> 3) & 1) * 8;
#pragma unroll 1
    for (int half = 0; half < 2; half++) {
        uint32_t a[4][4];
#pragma unroll
        for (int ks = 0; ks < 4; ks++) {
            uint32_t addr = base + A_OFF +
                (uint32_t)((ar * LDS + (half * 4 + ks) * 16 + ac) * 2);
            asm volatile(
                "ldmatrix.sync.aligned.m8n8.x4.shared.b16 {%0,%1,%2,%3}, [%4];"
                : "=r"(a[ks][0]), "=r"(a[ks][1]), "=r"(a[ks][2]), "=r"(a[ks][3])
                : "r"(addr));
        }
#pragma unroll
        for (int ks = 0; ks < 4; ks++) {
#pragma unroll
            for (int nf2 = 0; nf2 < 2; nf2++) {
                uint32_t addr = base + B_OFF +
                    (uint32_t)(((wc * 32 + nf2 * 16 + brow) * LDS +
                                (half * 4 + ks) * 16 + bcol) * 2);
                uint32_t b0, b1, b2, b3;
                asm volatile(
                    "ldmatrix.sync.aligned.m8n8.x4.shared.b16 {%0,%1,%2,%3}, [%4];"
                    : "=r"(b0), "=r"(b1), "=r"(b2), "=r"(b3)
                    : "r"(addr));
                mma16816(acc[nf2 * 2], a[ks], b0, b1);
                mma16816(acc[nf2 * 2 + 1], a[ks], b2, b3);
            }
        }
    }

    asm volatile("cp.async.wait_group 0;");   // pass-1 masks landed
    __syncthreads();   // all warps done with A smem before eT overlays it

    // ---- pass 1: I-rows, masks (I,J) from smem; write eT (overlays A) ----
    char* eT = smem;                          // [J-col 64][I-row 64], 144B rows
    const int il0 = wr * 16 + (l >> 2), il1 = il0 + 8;
    const int rl = il0 & 31;                  // row within half buffer
    const int gr0 = m0 + il0, gr1 = m0 + il1;
    float pA0 = 0.f, pA1 = 0.f, nA0 = 0.f, nA1 = 0.f;

#pragma unroll
    for (int nf = 0; nf < 4; nf++) {
        const int jcl = wc * 32 + nf * 8 + (l & 3) * 2;      // col in J block
        uint32_t mp = MB + (uint32_t)rl * MROW + (uint32_t)jcl * 4;
        uint32_t mq = mp + MH_Q;
        int2 P0, Q0, P1, Q1;
        asm volatile("ld.shared.v2.b32 {%0,%1}, [%2];" : "=r"(P0.x), "=r"(P0.y) : "r"(mp));
        asm volatile("ld.shared.v2.b32 {%0,%1}, [%2];" : "=r"(Q0.x), "=r"(Q0.y) : "r"(mq));
        asm volatile("ld.shared.v2.b32 {%0,%1}, [%2];" : "=r"(P1.x), "=r"(P1.y) : "r"(mp + 8 * MROW));
        asm volatile("ld.shared.v2.b32 {%0,%1}, [%2];" : "=r"(Q1.x), "=r"(Q1.y) : "r"(mq + 8 * MROW));

        float e00 = ex2f(acc[nf][0]);
        float e01 = ex2f(acc[nf][1]);
        float e10 = ex2f(acc[nf][2]);
        float e11 = ex2f(acc[nf][3]);

        if (!isDiag) {
            *(__nv_bfloat16*)(eT + (size_t)jcl * ETROW + il0 * 2) = __float2bfloat16_rn(e00);
            *(__nv_bfloat16*)(eT + (size_t)(jcl + 1) * ETROW + il0 * 2) = __float2bfloat16_rn(e01);
            *(__nv_bfloat16*)(eT + (size_t)jcl * ETROW + il1 * 2) = __float2bfloat16_rn(e10);
            *(__nv_bfloat16*)(eT + (size_t)(jcl + 1) * ETROW + il1 * 2) = __float2bfloat16_rn(e11);
        } else {
            const int jc = j0 + jcl;
            if (gr0 == jc)     { P0.x = 0; Q0.x = 0; }
            if (gr0 == jc + 1) { P0.y = 0; Q0.y = 0; }
            if (gr1 == jc)     { P1.x = 0; Q1.x = 0; }
            if (gr1 == jc + 1) { P1.y = 0; Q1.y = 0; }
        }
        pA0 = fmaf(e00, m2f(P0.x), fmaf(e01, m2f(P0.y), pA0));
        nA0 = fmaf(e00, m2f(Q0.x), fmaf(e01, m2f(Q0.y), nA0));
        pA1 = fmaf(e10, m2f(P1.x), fmaf(e11, m2f(P1.y), pA1));
        nA1 = fmaf(e10, m2f(Q1.x), fmaf(e11, m2f(Q1.y), nA1));
    }

#pragma unroll
    for (int o = 1; o < 4; o <<= 1) {
        pA0 += __shfl_xor_sync(0xffffffffu, pA0, o);
        pA1 += __shfl_xor_sync(0xffffffffu, pA1, o);
        nA0 += __shfl_xor_sync(0xffffffffu, nA0, o);
        nA1 += __shfl_xor_sync(0xffffffffu, nA1, o);
    }
    if ((l & 3) == 0) {
        atomicAdd(&g_pos[gr0], pA0);
        atomicAdd(&g_neg[gr0], nA0);
        atomicAdd(&g_pos[gr1], pA1);
        atomicAdd(&g_neg[gr1], nA1);
    }

    if (!isDiag) {
        barh(h);   // half done reading its pass-1 buffer

        // ---- pass-2 masks: half h copies rows j0+h*32..+32, cols m0..+64 ----
#pragma unroll
        for (int k2 = 0; k2 < 8; k2++) {
            int i = tq + k2 * 128;        // 0..1023 chunks
            const int* mp = (i & 512) ? nm : pm;
            uint32_t moff = (i & 512) ? MH_Q : 0u;
            int r = (i >> 4) & 31, ch = i & 15;
            cp16(MB + moff + (uint32_t)r * MROW + (uint32_t)ch * 16,
                 mp + (size_t)(j0 + h * 32 + r) * N + m0 + ch * 4);
        }
        asm volatile("cp.async.commit_group;");

        __syncthreads();   // eT fully written by both halves

        asm volatile("cp.async.wait_group 0;");
        barh(h);           // whole half's pass-2 copies landed

        // ---- pass 2: J-rows (warp w -> rows w*8..+8), I-cols 0..63 ----
        const int jl = w * 8 + (l >> 2);
        const int rl2 = jl & 31;
        const int hr = j0 + jl;
        float p2 = 0.f, n2 = 0.f;
#pragma unroll
        for (int nf = 0; nf < 8; nf++) {
            const int icl = nf * 8 + (l & 3) * 2;            // col in I block
            uint32_t mp = MB + (uint32_t)rl2 * MROW + (uint32_t)icl * 4;
            uint32_t mq = mp + MH_Q;
            int2 P0, Q0;
            asm volatile("ld.shared.v2.b32 {%0,%1}, [%2];" : "=r"(P0.x), "=r"(P0.y) : "r"(mp));
            asm volatile("ld.shared.v2.b32 {%0,%1}, [%2];" : "=r"(Q0.x), "=r"(Q0.y) : "r"(mq));

            __nv_bfloat162 ea = *(const __nv_bfloat162*)(eT + (size_t)jl * ETROW + icl * 2);
            float f0 = __bfloat162float(ea.x), f1 = __bfloat162float(ea.y);
            p2 = fmaf(f0, m2f(P0.x), fmaf(f1, m2f(P0.y), p2));
            n2 = fmaf(f0, m2f(Q0.x), fmaf(f1, m2f(Q0.y), n2));
        }
#pragma unroll
        for (int o = 1; o < 4; o <<= 1) {
            p2 += __shfl_xor_sync(0xffffffffu, p2, o);
            n2 += __shfl_xor_sync(0xffffffffu, n2, o);
        }
        if ((l & 3) == 0) {
            atomicAdd(&g_pos[hr], p2);
            atomicAdd(&g_neg[hr], n2);
        }
    }
}

// ---------------------------------------------------------------------------
// Kernel 3: final loss reduction. One block.
// ---------------------------------------------------------------------------
__global__ void loss_kernel(float* __restrict__ out) {
    __shared__ double sred[32];
    double s = 0.0;
    for (int r = threadIdx.x; r < N; r += blockDim.x) {
        float pos = g_pos[r];
        float neg = g_neg[r];
        s += (double)logf(pos / (pos + neg));
    }
#pragma unroll
    for (int o = 16; o > 0; o >>= 1) s += __shfl_xor_sync(0xffffffffu, s, o);
    int warp = threadIdx.x >> 5, lane = threadIdx.x & 31;
    if (lane == 0) sred[warp] = s;
    __syncthreads();
    if (warp == 0) {
        s = (lane < (int)(blockDim.x >> 5)) ? sred[lane] : 0.0;
#pragma unroll
        for (int o = 16; o > 0; o >>= 1) s += __shfl_xor_sync(0xffffffffu, s, o);
        if (lane == 0) out[0] = (float)(-s / (double)N);
    }
}

extern "C" void kernel_launch(void* const* d_in, const int* in_sizes, int n_in,
                              void* d_out, int out_size) {
    const float* features = (const float*)d_in[0];
    const int* pos_mask = (const int*)d_in[1];
    const int* neg_mask = (const int*)d_in[2];
    float* out = (float*)d_out;

    cudaFuncSetAttribute(simloss_sym, cudaFuncAttributeMaxDynamicSharedMemorySize,
                         SMEM_BYTES);

    normalize_kernel<<<N / 16, 256>>>(features);
    simloss_sym<<<NCTAS, NTHREADS, SMEM_BYTES>>>(pos_mask, neg_mask);
    loss_kernel<<<1, 1024>>>(out);
}

// round 15
// speedup vs baseline: 1.0241x; 1.0241x over previous
#include <cuda_runtime.h>
#include <cuda_bf16.h>
#include <cstdint>

#define N 8192
#define D 128
#define NB 128                   // 64-row blocks per dimension
#define NCTAS 8256               // NB*(NB+1)/2 triangular block pairs
#define LDS 136                  // feature tile smem row stride (bf16)
#define FN_SCALE 4.539815982f    // sqrt(log2(e)/0.07)

// dynamic smem layout (bytes)
#define A_OFF  0u                // A tile 64x136 bf16 (17408); reused as eT
#define B_OFF  17408u            // B tile 64x136 bf16 (17408)
#define M1_OFF 34816u            // pass-1 masks: P(64x288) + Q(64x288)
#define M2_OFF 71680u            // pass-2 masks: P(64x288) + Q(64x288)
#define MQOFF  18432u            // Q offset within a mask region
#define MROW   288u              // mask smem row stride (72 words, 8 mod 32)
#define ETROW  144u              // eT row stride bytes
#define SMEM_BYTES 108544

#define NTHREADS 256

__device__ __nv_bfloat16 g_fn[N * D];
__device__ float g_pos[N];
__device__ float g_neg[N];

__device__ __forceinline__ float ex2f(float x) {
    float y;
    asm("ex2.approx.ftz.f32 %0, %1;" : "=f"(y) : "f"(x));
    return y;
}

// mask (0/1) -> float via single IMAD: bits = m * 0x3F800000
__device__ __forceinline__ float m2f(int m) {
    return __int_as_float(m * 0x3F800000);
}

__device__ __forceinline__ void mma16816(float d[4], const uint32_t a[4],
                                         uint32_t b0, uint32_t b1) {
    asm volatile(
        "mma.sync.aligned.m16n8k16.row.col.f32.bf16.bf16.f32 "
        "{%0,%1,%2,%3}, {%4,%5,%6,%7}, {%8,%9}, {%0,%1,%2,%3};"
        : "+f"(d[0]), "+f"(d[1]), "+f"(d[2]), "+f"(d[3])
        : "r"(a[0]), "r"(a[1]), "r"(a[2]), "r"(a[3]), "r"(b0), "r"(b1));
}

__device__ __forceinline__ void cp16(uint32_t dst, const void* src) {
    asm volatile("cp.async.cg.shared.global [%0], [%1], 16;" :: "r"(dst), "l"(src));
}

// copy a 64x64 int32 block pair (P then Q) into a mask region, all 256 threads
__device__ __forceinline__ void copy_mask_block(uint32_t mb,
                                                const int* __restrict__ pm,
                                                const int* __restrict__ nm,
                                                int row0, int col0, int tid) {
#pragma unroll
    for (int k2 = 0; k2 < 8; k2++) {
        int i = tid + k2 * 256;           // 0..2047 16B chunks
        const int* mp = (i & 1024) ? nm : pm;
        uint32_t moff = (i & 1024) ? MQOFF : 0u;
        int r = (i >> 4) & 63, ch = i & 15;
        cp16(mb + moff + (uint32_t)r * MROW + (uint32_t)ch * 16,
             mp + (size_t)(row0 + r) * N + col0 + ch * 4);
    }
}

// decode upper-triangular 64-block pair index k -> (I, J), 0 <= I <= J < 128
__device__ __forceinline__ void decode_pair(int k, int& I, int& J) {
    I = (int)((257.0f - sqrtf(66049.0f - 8.0f * (float)k)) * 0.5f);
    while ((I * (257 - I)) / 2 > k) I--;
    while (((I + 1) * (256 - I)) / 2 <= k) I++;
    J = I + (k - (I * (257 - I)) / 2);
}

// ---------------------------------------------------------------------------
// Kernel 1: L2-normalize rows (exp scale folded) + zero accumulators.
// ---------------------------------------------------------------------------
__global__ void normalize_kernel(const float* __restrict__ f) {
    int z = blockIdx.x * 256 + threadIdx.x;
    if (z < N) g_pos[z] = 0.f;
    else if (z < 2 * N) g_neg[z - N] = 0.f;

    int warp = threadIdx.x >> 5, lane = threadIdx.x & 31;
    int row0 = blockIdx.x * 16 + warp * 2;
    const float4 v0 = ((const float4*)(f + (size_t)row0 * D))[lane];
    const float4 v1 = ((const float4*)(f + (size_t)(row0 + 1) * D))[lane];
    float s0 = v0.x * v0.x + v0.y * v0.y + v0.z * v0.z + v0.w * v0.w;
    float s1 = v1.x * v1.x + v1.y * v1.y + v1.z * v1.z + v1.w * v1.w;
#pragma unroll
    for (int o = 16; o > 0; o >>= 1) {
        s0 += __shfl_xor_sync(0xffffffffu, s0, o);
        s1 += __shfl_xor_sync(0xffffffffu, s1, o);
    }
    float r0 = FN_SCALE / fmaxf(sqrtf(s0), 1e-8f);
    float r1 = FN_SCALE / fmaxf(sqrtf(s1), 1e-8f);
    union { __nv_bfloat16 h[4]; uint2 u; } p0, p1;
    p0.h[0] = __float2bfloat16_rn(v0.x * r0);
    p0.h[1] = __float2bfloat16_rn(v0.y * r0);
    p0.h[2] = __float2bfloat16_rn(v0.z * r0);
    p0.h[3] = __float2bfloat16_rn(v0.w * r0);
    p1.h[0] = __float2bfloat16_rn(v1.x * r1);
    p1.h[1] = __float2bfloat16_rn(v1.y * r1);
    p1.h[2] = __float2bfloat16_rn(v1.z * r1);
    p1.h[3] = __float2bfloat16_rn(v1.w * r1);
    ((uint2*)(g_fn + (size_t)row0 * D))[lane] = p0.u;
    ((uint2*)(g_fn + (size_t)(row0 + 1) * D))[lane] = p1.u;
}

// ---------------------------------------------------------------------------
// Kernel 2: 64x64 block-pair Gram tiles, 256 thr/CTA, 2 CTAs/SM.
// ALL DRAM demand (features, pass-1 masks, pass-2 masks) issued as THREE
// NON-EMPTY cp.async groups at CTA start. Every CTA drains wait_group 0
// before any thread can exit (no in-flight copies into recycled smem).
// MMA: warp w -> rows (w>>1)*16..+16, cols (w&1)*32..+32. acc[4][4].
// ---------------------------------------------------------------------------
__global__ __launch_bounds__(NTHREADS, 2) void simloss_sym(const int* __restrict__ pm,
                                                           const int* __restrict__ nm) {
    extern __shared__ __align__(16) char smem[];
    const uint32_t base = (uint32_t)__cvta_generic_to_shared(smem);
    const int tid = threadIdx.x;
    const int w = tid >> 5, l = tid & 31;
    const int wr = w >> 1, wc = w & 1;

    int I, J;
    decode_pair(blockIdx.x, I, J);
    const int m0 = I * 64, j0 = J * 64;
    const bool isDiag = (I == J);

    // ---- group 0: feature tiles A (64 I-rows) + B (64 J-rows) ----
#pragma unroll
    for (int k2 = 0; k2 < 4; k2++) {
        int i = tid + k2 * 256;           // 0..1023 chunks
        int r = i >> 4, c = i & 15;
        cp16(base + A_OFF + (uint32_t)((r * LDS + c * 8) * 2),
             g_fn + (size_t)(m0 + r) * D + c * 8);
        cp16(base + B_OFF + (uint32_t)((r * LDS + c * 8) * 2),
             g_fn + (size_t)(j0 + r) * D + c * 8);
    }
    asm volatile("cp.async.commit_group;");

    // ---- group 1: pass-1 masks (rows m0..+64, cols j0..+64) ----
    copy_mask_block(base + M1_OFF, pm, nm, m0, j0, tid);
    asm volatile("cp.async.commit_group;");

    // ---- group 2: pass-2 masks (rows j0..+64, cols m0..+64) ----
    // UNCONDITIONAL: diag CTAs copy (m0,m0) and never read it, keeping all
    // CTAs at exactly 3 non-empty groups so wait_group 2/1/0 is always valid.
    copy_mask_block(base + M2_OFF, pm, nm, j0, m0, tid);
    asm volatile("cp.async.commit_group;");

    asm volatile("cp.async.wait_group 2;");   // own features issued...
    __syncthreads();                          // ...all threads' features visible

    // ---- MMA: 16 rows x 32 cols per warp, A frags in two k-halves ----
    float acc[4][4];
#pragma unroll
    for (int i = 0; i < 4; i++) {
        acc[i][0] = 0.f; acc[i][1] = 0.f; acc[i][2] = 0.f; acc[i][3] = 0.f;
    }
    const int ar = wr * 16 + (l & 15);
    const int ac = (l >> 4) * 8;
    const int brow = (l >> 4) * 8 + (l & 7);
    const int bcol = ((l >> 3) & 1) * 8;
#pragma unroll 1
    for (int half = 0; half < 2; half++) {
        uint32_t a[4][4];
#pragma unroll
        for (int ks = 0; ks < 4; ks++) {
            uint32_t addr = base + A_OFF +
                (uint32_t)((ar * LDS + (half * 4 + ks) * 16 + ac) * 2);
            asm volatile(
                "ldmatrix.sync.aligned.m8n8.x4.shared.b16 {%0,%1,%2,%3}, [%4];"
                : "=r"(a[ks][0]), "=r"(a[ks][1]), "=r"(a[ks][2]), "=r"(a[ks][3])
                : "r"(addr));
        }
#pragma unroll
        for (int ks = 0; ks < 4; ks++) {
#pragma unroll
            for (int nf2 = 0; nf2 < 2; nf2++) {
                uint32_t addr = base + B_OFF +
                    (uint32_t)(((wc * 32 + nf2 * 16 + brow) * LDS +
                                (half * 4 + ks) * 16 + bcol) * 2);
                uint32_t b0, b1, b2, b3;
                asm volatile(
                    "ldmatrix.sync.aligned.m8n8.x4.shared.b16 {%0,%1,%2,%3}, [%4];"
                    : "=r"(b0), "=r"(b1), "=r"(b2), "=r"(b3)
                    : "r"(addr));
                mma16816(acc[nf2 * 2], a[ks], b0, b1);
                mma16816(acc[nf2 * 2 + 1], a[ks], b2, b3);
            }
        }
    }

    asm volatile("cp.async.wait_group 1;");   // own pass-1 copies done...
    __syncthreads();   // ...all threads' M1 visible; all A reads done (eT safe)

    // ---- pass 1: I-rows, masks (I,J) from smem; write eT (overlays A) ----
    char* eT = smem;                          // [J-col 64][I-row 64], 144B rows
    const int il0 = wr * 16 + (l >> 2), il1 = il0 + 8;
    const int gr0 = m0 + il0, gr1 = m0 + il1;
    float pA0 = 0.f, pA1 = 0.f, nA0 = 0.f, nA1 = 0.f;

#pragma unroll
    for (int nf = 0; nf < 4; nf++) {
        const int jcl = wc * 32 + nf * 8 + (l & 3) * 2;      // col in J block
        uint32_t mp = base + M1_OFF + (uint32_t)il0 * MROW + (uint32_t)jcl * 4;
        uint32_t mq = mp + MQOFF;
        int2 P0, Q0, P1, Q1;
        asm volatile("ld.shared.v2.b32 {%0,%1}, [%2];" : "=r"(P0.x), "=r"(P0.y) : "r"(mp));
        asm volatile("ld.shared.v2.b32 {%0,%1}, [%2];" : "=r"(Q0.x), "=r"(Q0.y) : "r"(mq));
        asm volatile("ld.shared.v2.b32 {%0,%1}, [%2];" : "=r"(P1.x), "=r"(P1.y) : "r"(mp + 8 * MROW));
        asm volatile("ld.shared.v2.b32 {%0,%1}, [%2];" : "=r"(Q1.x), "=r"(Q1.y) : "r"(mq + 8 * MROW));

        float e00 = ex2f(acc[nf][0]);
        float e01 = ex2f(acc[nf][1]);
        float e10 = ex2f(acc[nf][2]);
        float e11 = ex2f(acc[nf][3]);

        if (!isDiag) {
            *(__nv_bfloat16*)(eT + (size_t)jcl * ETROW + il0 * 2) = __float2bfloat16_rn(e00);
            *(__nv_bfloat16*)(eT + (size_t)(jcl + 1) * ETROW + il0 * 2) = __float2bfloat16_rn(e01);
            *(__nv_bfloat16*)(eT + (size_t)jcl * ETROW + il1 * 2) = __float2bfloat16_rn(e10);
            *(__nv_bfloat16*)(eT + (size_t)(jcl + 1) * ETROW + il1 * 2) = __float2bfloat16_rn(e11);
        } else {
            const int jc = j0 + jcl;
            if (gr0 == jc)     { P0.x = 0; Q0.x = 0; }
            if (gr0 == jc + 1) { P0.y = 0; Q0.y = 0; }
            if (gr1 == jc)     { P1.x = 0; Q1.x = 0; }
            if (gr1 == jc + 1) { P1.y = 0; Q1.y = 0; }
        }
        pA0 = fmaf(e00, m2f(P0.x), fmaf(e01, m2f(P0.y), pA0));
        nA0 = fmaf(e00, m2f(Q0.x), fmaf(e01, m2f(Q0.y), nA0));
        pA1 = fmaf(e10, m2f(P1.x), fmaf(e11, m2f(P1.y), pA1));
        nA1 = fmaf(e10, m2f(Q1.x), fmaf(e11, m2f(Q1.y), nA1));
    }

#pragma unroll
    for (int o = 1; o < 4; o <<= 1) {
        pA0 += __shfl_xor_sync(0xffffffffu, pA0, o);
        pA1 += __shfl_xor_sync(0xffffffffu, pA1, o);
        nA0 += __shfl_xor_sync(0xffffffffu, nA0, o);
        nA1 += __shfl_xor_sync(0xffffffffu, nA1, o);
    }
    if ((l & 3) == 0) {
        atomicAdd(&g_pos[gr0], pA0);
        atomicAdd(&g_neg[gr0], nA0);
        atomicAdd(&g_pos[gr1], pA1);
        atomicAdd(&g_neg[gr1], nA1);
    }

    // ---- drain ALL async copies, then make every thread's writes visible.
    // UNCONDITIONAL: fixes (a) per-thread wait_group semantics (reader needs
    // writers' copies visible -> wait BEFORE barrier), (b) diag CTAs exiting
    // with in-flight cp.asyncs into soon-recycled smem.
    asm volatile("cp.async.wait_group 0;");
    __syncthreads();   // eT writes + all threads' M2 copies visible

    // ---- pass 2 (off-diag): J-rows, masks (J,I) from M2, exp from eT ----
    if (!isDiag) {
        const int jl = w * 8 + (l >> 2);          // warp w -> J-rows w*8..+8
        const int hr = j0 + jl;
        float p2 = 0.f, n2 = 0.f;
#pragma unroll
        for (int nf = 0; nf < 8; nf++) {
            const int icl = nf * 8 + (l & 3) * 2;            // col in I block
            uint32_t mp = base + M2_OFF + (uint32_t)jl * MROW + (uint32_t)icl * 4;
            uint32_t mq = mp + MQOFF;
            int2 P0, Q0;
            asm volatile("ld.shared.v2.b32 {%0,%1}, [%2];" : "=r"(P0.x), "=r"(P0.y) : "r"(mp));
            asm volatile("ld.shared.v2.b32 {%0,%1}, [%2];" : "=r"(Q0.x), "=r"(Q0.y) : "r"(mq));

            __nv_bfloat162 ea = *(const __nv_bfloat162*)(eT + (size_t)jl * ETROW + icl * 2);
            float f0 = __bfloat162float(ea.x), f1 = __bfloat162float(ea.y);
            p2 = fmaf(f0, m2f(P0.x), fmaf(f1, m2f(P0.y), p2));
            n2 = fmaf(f0, m2f(Q0.x), fmaf(f1, m2f(Q0.y), n2));
        }
#pragma unroll
        for (int o = 1; o < 4; o <<= 1) {
            p2 += __shfl_xor_sync(0xffffffffu, p2, o);
            n2 += __shfl_xor_sync(0xffffffffu, n2, o);
        }
        if ((l & 3) == 0) {
            atomicAdd(&g_pos[hr], p2);
            atomicAdd(&g_neg[hr], n2);
        }
    }
}

// ---------------------------------------------------------------------------
// Kernel 3: final loss reduction. One block.
// ---------------------------------------------------------------------------
__global__ void loss_kernel(float* __restrict__ out) {
    __shared__ double sred[32];
    double s = 0.0;
    for (int r = threadIdx.x; r < N; r += blockDim.x) {
        float pos = g_pos[r];
        float neg = g_neg[r];
        s += (double)logf(pos / (pos + neg));
    }
#pragma unroll
    for (int o = 16; o > 0; o >>= 1) s += __shfl_xor_sync(0xffffffffu, s, o);
    int warp = threadIdx.x >> 5, lane = threadIdx.x & 31;
    if (lane == 0) sred[warp] = s;
    __syncthreads();
    if (warp == 0) {
        s = (lane < (int)(blockDim.x >> 5)) ? sred[lane] : 0.0;
#pragma unroll
        for (int o = 16; o > 0; o >>= 1) s += __shfl_xor_sync(0xffffffffu, s, o);
        if (lane == 0) out[0] = (float)(-s / (double)N);
    }
}

extern "C" void kernel_launch(void* const* d_in, const int* in_sizes, int n_in,
                              void* d_out, int out_size) {
    const float* features = (const float*)d_in[0];
    const int* pos_mask = (const int*)d_in[1];
    const int* neg_mask = (const int*)d_in[2];
    float* out = (float*)d_out;

    cudaFuncSetAttribute(simloss_sym, cudaFuncAttributeMaxDynamicSharedMemorySize,
                         SMEM_BYTES);

    normalize_kernel<<<N / 16, 256>>>(features);
    simloss_sym<<<NCTAS, NTHREADS, SMEM_BYTES>>>(pos_mask, neg_mask);
    loss_kernel<<<1, 1024>>>(out);
}